// round 15
// baseline (speedup 1.0000x reference)
#include <cuda_runtime.h>
#include <cuda_bf16.h>
#include <stdint.h>
#include <math.h>

#define BATCH 8
#define H0 512

typedef unsigned short u16;

// ------------------------- scratch globals (no allocs) ---------------------
// pool1 per stream, halo-padded channel-last bf16: [b][258][258][32]
#define P1W 258
#define NP1 ((size_t)BATCH * P1W * P1W * 32)
__device__ u16 g_p1[2][NP1];
// concat halo-padded channel-last bf16: [b][130][130][128]
#define CCW 130
#define NCC ((size_t)BATCH * CCW * CCW * 128)
__device__ u16 g_cc[NCC];
__device__ float g_mean[BATCH * 128];

// pre-packed weights as uint4 {bhi0, bhi1, blo0, blo1}: [...][oc][sk][t]
__device__ uint4 g_wc1[64][2][4];
__device__ uint4 g_wc2[18][64][2][4];
__device__ uint4 g_wf[9][128][8][4];

// ------------------------- numeric helpers ---------------------------------
__device__ __forceinline__ u16 bf_hi(float v) {
    return __bfloat16_as_ushort(__float2bfloat16(v));
}
__device__ __forceinline__ u16 bf_lo(float v) {
    float h = __bfloat162float(__float2bfloat16(v));
    return __bfloat16_as_ushort(__float2bfloat16(v - h));
}
__device__ __forceinline__ uint32_t pack_hi2(float v0, float v1) {
    return (uint32_t)bf_hi(v0) | ((uint32_t)bf_hi(v1) << 16);
}
__device__ __forceinline__ uint32_t pack_lo2(float v0, float v1) {
    return (uint32_t)bf_lo(v0) | ((uint32_t)bf_lo(v1) << 16);
}

// m16n8k16 bf16 HMMA, D += A*B (fp32 accumulate)
__device__ __forceinline__ void mma16816(float* d, const uint32_t* a, uint32_t b0, uint32_t b1) {
    asm volatile(
        "mma.sync.aligned.m16n8k16.row.col.f32.bf16.bf16.f32 "
        "{%0,%1,%2,%3}, {%4,%5,%6,%7}, {%8,%9}, {%0,%1,%2,%3};"
        : "+f"(d[0]), "+f"(d[1]), "+f"(d[2]), "+f"(d[3])
        : "r"(a[0]), "r"(a[1]), "r"(a[2]), "r"(a[3]), "r"(b0), "r"(b1));
}

__device__ __forceinline__ uint32_t ld32(const u16* p) {
    return *(const uint32_t*)p;
}

// ------------------------- init kernels ------------------------------------
__global__ void zero_mean_kernel() {
    int i = threadIdx.x;
    if (i < BATCH * 128) g_mean[i] = 0.f;
}

__global__ void halo_p1_kernel() {
    int idx = blockIdx.x * 256 + threadIdx.x;       // 8 b x 1028 px x 32 c
    if (idx >= BATCH * 1028 * 32) return;
    int c = idx & 31;
    int r = idx >> 5;
    int b = r / 1028;
    int p = r - b * 1028;
    int y, x;
    if (p < 258)      { y = 0;           x = p; }
    else if (p < 516) { y = 257;         x = p - 258; }
    else if (p < 772) { y = p - 516 + 1; x = 0; }
    else              { y = p - 772 + 1; x = 257; }
    size_t i = (((size_t)(b * P1W + y)) * P1W + x) * 32 + c;
    g_p1[0][i] = 0;
    g_p1[1][i] = 0;
}

__global__ void halo_cc_kernel() {
    int idx = blockIdx.x * 256 + threadIdx.x;       // 8 b x 516 px x 128 c
    if (idx >= BATCH * 516 * 128) return;
    int c = idx & 127;
    int r = idx >> 7;
    int b = r / 516;
    int p = r - b * 516;
    int y, x;
    if (p < 130)      { y = 0;           x = p; }
    else if (p < 260) { y = 129;         x = p - 130; }
    else if (p < 388) { y = p - 260 + 1; x = 0; }
    else              { y = p - 388 + 1; x = 129; }
    g_cc[(((size_t)(b * CCW + y)) * CCW + x) * 128 + c] = 0;
}

// ------------------------- weight transforms -------------------------------
__device__ __forceinline__ float w1elem(const float* w, int ocl, int kk) {
    if (kk >= 27) return 0.f;
    int tap = kk / 3;
    int ic = kk - 3 * tap;
    return w[ocl * 27 + ic * 9 + tap];
}

__global__ void xform_w1(const float* __restrict__ wr, const float* __restrict__ wi) {
    int idx = blockIdx.x * 256 + threadIdx.x;       // 64 oc x 2 sk x 4 t
    if (idx >= 512) return;
    int oc = idx >> 3, sk = (idx >> 2) & 1, t = idx & 3;
    const float* w = (oc < 32) ? wr : wi;
    int ocl = oc & 31;
    int pA = t + 8 * sk, pB = pA + 4;
    float a0 = w1elem(w, ocl, 2 * pA), a1 = w1elem(w, ocl, 2 * pA + 1);
    float b0 = w1elem(w, ocl, 2 * pB), b1 = w1elem(w, ocl, 2 * pB + 1);
    g_wc1[oc][sk][t] = make_uint4(pack_hi2(a0, a1), pack_hi2(b0, b1),
                                  pack_lo2(a0, a1), pack_lo2(b0, b1));
}

__global__ void xform_w2(const float* __restrict__ w, int sidx) {
    int idx = blockIdx.x * 256 + threadIdx.x;       // 9 tap x 64 oc x 2 sk x 4 t
    if (idx >= 9 * 512) return;
    int tap = idx / 512;
    int rem = idx & 511;
    int oc = rem >> 3, sk = (rem >> 2) & 1, t = rem & 3;
    int pA = t + 8 * sk, pB = pA + 4;
    float a0 = w[oc * 288 + (2 * pA) * 9 + tap],     a1 = w[oc * 288 + (2 * pA + 1) * 9 + tap];
    float b0 = w[oc * 288 + (2 * pB) * 9 + tap],     b1 = w[oc * 288 + (2 * pB + 1) * 9 + tap];
    g_wc2[sidx * 9 + tap][oc][sk][t] = make_uint4(pack_hi2(a0, a1), pack_hi2(b0, b1),
                                                  pack_lo2(a0, a1), pack_lo2(b0, b1));
}

__global__ void xform_wf(const float* __restrict__ w) {
    int idx = blockIdx.x * 256 + threadIdx.x;       // 9 tap x 128 oc x 8 sk x 4 t
    if (idx >= 9 * 4096) return;
    int tap = idx >> 12;
    int rem = idx & 4095;
    int oc = rem >> 5, sk = (rem >> 2) & 7, t = rem & 3;
    int pA = t + 8 * sk, pB = pA + 4;
    float a0 = w[(oc * 128 + 2 * pA) * 9 + tap],     a1 = w[(oc * 128 + 2 * pA + 1) * 9 + tap];
    float b0 = w[(oc * 128 + 2 * pB) * 9 + tap],     b1 = w[(oc * 128 + 2 * pB + 1) * 9 + tap];
    g_wf[tap][oc][sk][t] = make_uint4(pack_hi2(a0, a1), pack_hi2(b0, b1),
                                      pack_lo2(a0, a1), pack_lo2(b0, b1));
}

// ======================= conv1 (both streams in one GEMM) ==================
__device__ __forceinline__ float conv1_fetch(const float* xb, int kk, int py, int px) {
    if (kk >= 27) return 0.f;
    int tap = kk / 3;
    int ic = kk - tap * 3;
    int kh = tap / 3;
    int kw = tap - kh * 3;
    int gy = py + kh - 1;
    int gx = px + kw - 1;
    if (gy < 0 || gy >= H0 || gx < 0 || gx >= H0) return 0.f;
    return xb[(size_t)ic * H0 * H0 + (size_t)gy * H0 + gx];
}

// grid 8192: (b, pooled row Y 0..255, x-group of 128 pre-pool cols).
// M=256 (2 dy frags x 128 xx), N=64, K=32 (27 used). A bf16-hi only.
__global__ void __launch_bounds__(256, 2)
conv1_mma(const float* __restrict__ x,
          const float* __restrict__ b_rgb,
          const float* __restrict__ b_ir) {
    __shared__ float s[128 * 65];
    int tid = threadIdx.x;
    int wid = tid >> 5;
    int lane = tid & 31;
    int g = lane >> 2;
    int t = lane & 3;
    int cbase = 2 * t;
    int bid = blockIdx.x;
    int x0 = (bid & 3) * 128;
    int Y = (bid >> 2) & 255;
    int b = bid >> 10;
    const float* xb = x + (size_t)b * 3 * H0 * H0;

    int xx0 = wid * 16 + g;
    int xx1 = xx0 + 8;

    float d[2][8][4];
#pragma unroll
    for (int f = 0; f < 2; f++)
#pragma unroll
        for (int nb = 0; nb < 8; nb++)
#pragma unroll
            for (int i = 0; i < 4; i++) d[f][nb][i] = 0.f;

#pragma unroll
    for (int sk = 0; sk < 2; sk++) {
        int k0 = sk * 16 + cbase;
        uint32_t aHi[2][4];
#pragma unroll
        for (int f = 0; f < 2; f++) {
            int py = 2 * Y + f;
            float v00 = conv1_fetch(xb, k0,     py, x0 + xx0);
            float v01 = conv1_fetch(xb, k0 + 1, py, x0 + xx0);
            float v08 = conv1_fetch(xb, k0 + 8, py, x0 + xx0);
            float v09 = conv1_fetch(xb, k0 + 9, py, x0 + xx0);
            float v10 = conv1_fetch(xb, k0,     py, x0 + xx1);
            float v11 = conv1_fetch(xb, k0 + 1, py, x0 + xx1);
            float v18 = conv1_fetch(xb, k0 + 8, py, x0 + xx1);
            float v19 = conv1_fetch(xb, k0 + 9, py, x0 + xx1);
            aHi[f][0] = pack_hi2(v00, v01);
            aHi[f][1] = pack_hi2(v10, v11);
            aHi[f][2] = pack_hi2(v08, v09);
            aHi[f][3] = pack_hi2(v18, v19);
        }
#pragma unroll
        for (int nb = 0; nb < 8; nb++) {
            int n = nb * 8 + g;
            uint4 w = g_wc1[n][sk][t];
#pragma unroll
            for (int f = 0; f < 2; f++) {
                mma16816(d[f][nb], aHi[f], w.x, w.y);
                mma16816(d[f][nb], aHi[f], w.z, w.w);
            }
        }
    }

    // 2-pass epilogue: pass f writes frag f rows (xx), pool across passes.
    float pm[16];
#pragma unroll
    for (int f = 0; f < 2; f++) {
#pragma unroll
        for (int nb = 0; nb < 8; nb++) {
            int c = nb * 8 + cbase;
            s[xx0 * 65 + c]     = d[f][nb][0];
            s[xx0 * 65 + c + 1] = d[f][nb][1];
            s[xx1 * 65 + c]     = d[f][nb][2];
            s[xx1 * 65 + c + 1] = d[f][nb][3];
        }
        __syncthreads();
#pragma unroll
        for (int k = 0; k < 16; k++) {
            int oi = k * 256 + tid;
            int oc = oi & 63;
            int j = oi >> 6;
            float m = fmaxf(s[(2 * j) * 65 + oc], s[(2 * j + 1) * 65 + oc]);
            if (f == 0) {
                pm[k] = m;
            } else {
                int st = oc >> 5;
                int ocl = oc & 31;
                float bi = st ? b_ir[ocl] : b_rgb[ocl];
                float v = fmaxf(fmaxf(pm[k], m) + bi, 0.f);
                size_t pix = (((size_t)(b * P1W + Y + 1)) * P1W + (x0 >> 1) + j + 1) * 32 + ocl;
                g_p1[st][pix] = bf_hi(v);
            }
        }
        __syncthreads();
    }
}

// ======================= conv2 (both streams, one launch) ==================
// grid 4096: (which, b, pooled row Y 0..127, x-group of 128 pre-pool cols).
// M=256, N=64 oc, K = 9 taps x 32 ic. A staged in smem (conflict-free).
#define TPX 40                                     // u16 per pixel slot (80B)
__global__ void __launch_bounds__(256, 2)
conv2_mma(const float* __restrict__ bias_r, const float* __restrict__ bias_i) {
    __shared__ u16 tile[4 * 132 * TPX];            // 42240 B
    int tid = threadIdx.x;
    int wid = tid >> 5;
    int lane = tid & 31;
    int g = lane >> 2;
    int t = lane & 3;
    int cbase = 2 * t;
    int bid = blockIdx.x;
    int x0 = (bid & 1) * 128;
    int Y = (bid >> 1) & 127;
    int b = (bid >> 8) & 7;
    int which = bid >> 11;
    const u16* ph = g_p1[which];
    const float* bias = which ? bias_i : bias_r;
    int ch_off = which * 64;
    int wm0 = which * 9;

    int xx0 = wid * 16 + g;
    int xx1 = xx0 + 8;

    // stage: rows (2Y+r), r=0..3; px x0..x0+129; all 32 ch. 2080 uint4.
    {
        const u16* src = ph + (((size_t)(b * P1W + 2 * Y)) * P1W + x0) * 32;
#pragma unroll
        for (int i = tid; i < 2080; i += 256) {
            int r = i / 520;
            int j = i - r * 520;
            int p = j >> 2;
            int q = j & 3;
            uint4 v = *(const uint4*)(src + ((size_t)r * P1W + p) * 32 + q * 8);
            *(uint4*)&tile[(r * 132 + p) * TPX + q * 8] = v;
        }
    }
    __syncthreads();

    float d[2][8][4];
#pragma unroll
    for (int f = 0; f < 2; f++)
#pragma unroll
        for (int nb = 0; nb < 8; nb++)
#pragma unroll
            for (int i = 0; i < 4; i++) d[f][nb][i] = 0.f;

#pragma unroll
    for (int tap = 0; tap < 9; tap++) {
        const int kh = tap / 3;
        const int kw = tap - kh * 3;
        const uint4(*wt)[2][4] = g_wc2[wm0 + tap];
        int base00 = ((0 + kh) * 132 + xx0 + kw) * TPX;
        int base01 = ((0 + kh) * 132 + xx1 + kw) * TPX;
        int base10 = ((1 + kh) * 132 + xx0 + kw) * TPX;
        int base11 = ((1 + kh) * 132 + xx1 + kw) * TPX;
#pragma unroll
        for (int sk = 0; sk < 2; sk++) {
            int ic = sk * 16 + cbase;
            uint32_t aHi[2][4];
            aHi[0][0] = ld32(tile + base00 + ic);
            aHi[0][1] = ld32(tile + base01 + ic);
            aHi[0][2] = ld32(tile + base00 + ic + 8);
            aHi[0][3] = ld32(tile + base01 + ic + 8);
            aHi[1][0] = ld32(tile + base10 + ic);
            aHi[1][1] = ld32(tile + base11 + ic);
            aHi[1][2] = ld32(tile + base10 + ic + 8);
            aHi[1][3] = ld32(tile + base11 + ic + 8);
#pragma unroll
            for (int nb = 0; nb < 8; nb++) {
                int n = nb * 8 + g;
                uint4 w = wt[n][sk][t];
#pragma unroll
                for (int f = 0; f < 2; f++) {
                    mma16816(d[f][nb], aHi[f], w.x, w.y);
                    mma16816(d[f][nb], aHi[f], w.z, w.w);
                }
            }
        }
    }

    // epilogue reuses tile as f32 buffer (33 KB <= 42.2 KB)
    __syncthreads();
    float* s = (float*)tile;
    float pm[16];
#pragma unroll
    for (int f = 0; f < 2; f++) {
#pragma unroll
        for (int nb = 0; nb < 8; nb++) {
            int c = nb * 8 + cbase;
            s[xx0 * 65 + c]     = d[f][nb][0];
            s[xx0 * 65 + c + 1] = d[f][nb][1];
            s[xx1 * 65 + c]     = d[f][nb][2];
            s[xx1 * 65 + c + 1] = d[f][nb][3];
        }
        __syncthreads();
#pragma unroll
        for (int k = 0; k < 16; k++) {
            int oi = k * 256 + tid;
            int oc = oi & 63;
            int j = oi >> 6;
            float m = fmaxf(s[(2 * j) * 65 + oc], s[(2 * j + 1) * 65 + oc]);
            if (f == 0) {
                pm[k] = m;
            } else {
                float v = fmaxf(fmaxf(pm[k], m) + bias[oc], 0.f);
                size_t pix = (((size_t)(b * CCW + Y + 1)) * CCW + (x0 >> 1) + j + 1) * 128 + ch_off + oc;
                g_cc[pix] = bf_hi(v);
            }
        }
        __syncthreads();
    }
}

// ======================= fuse (128->128 conv + relu + mean) ================
// grid 1024: (b, y-pair 0..63, oc-half). M=256 (2 y rows x 128 x), N=64,
// K = 9 taps x 128 ic, split into 2 ic-halves of 64 staged in dynamic smem.
// Tile: 4 rows x 132 px x 72-u16 stride (pixel stride 36 words -> LDS bank
// = 4g+t = lane, conflict-free). Reused as f32 epilogue buffer.
#define FTPX 72
#define FUSE_SMEM (4 * 132 * FTPX * 2)             // 76032 B
__global__ void __launch_bounds__(256, 2)
fuse_mma(const float* __restrict__ bias) {
    extern __shared__ u16 ftile[];
    int tid = threadIdx.x;
    int wid = tid >> 5;
    int lane = tid & 31;
    int g = lane >> 2;
    int t = lane & 3;
    int cbase = 2 * t;
    int bid = blockIdx.x;
    int nh = bid & 1;
    int yp = (bid >> 1) & 63;
    int b = bid >> 7;
    int y0 = 2 * yp;

    int xx0 = wid * 16 + g;
    int xx1 = xx0 + 8;

    float d[2][8][4];
#pragma unroll
    for (int f = 0; f < 2; f++)
#pragma unroll
        for (int nb = 0; nb < 8; nb++)
#pragma unroll
            for (int i = 0; i < 4; i++) d[f][nb][i] = 0.f;

#pragma unroll
    for (int skh = 0; skh < 2; skh++) {
        // stage padded rows y0..y0+3, px 0..129, channels [skh*64, skh*64+64)
        {
            const u16* src = g_cc + ((size_t)(b * CCW + y0)) * CCW * 128 + skh * 64;
            for (int i = tid; i < 4160; i += 256) {
                int r = i / 1040;
                int j = i - r * 1040;
                int p = j >> 3;
                int q = j & 7;
                uint4 v = *(const uint4*)(src + ((size_t)r * CCW + p) * 128 + q * 8);
                *(uint4*)&ftile[(r * 132 + p) * FTPX + q * 8] = v;
            }
        }
        __syncthreads();

#pragma unroll
        for (int tap = 0; tap < 9; tap++) {
            const int kh = tap / 3;
            const int kw = tap - kh * 3;
            const uint4(*wt)[8][4] = g_wf[tap];
            int base00 = ((0 + kh) * 132 + xx0 + kw) * FTPX;
            int base01 = ((0 + kh) * 132 + xx1 + kw) * FTPX;
            int base10 = ((1 + kh) * 132 + xx0 + kw) * FTPX;
            int base11 = ((1 + kh) * 132 + xx1 + kw) * FTPX;
#pragma unroll
            for (int sk = 0; sk < 4; sk++) {
                int ic = sk * 16 + cbase;
                uint32_t aHi[2][4];
                aHi[0][0] = ld32(ftile + base00 + ic);
                aHi[0][1] = ld32(ftile + base01 + ic);
                aHi[0][2] = ld32(ftile + base00 + ic + 8);
                aHi[0][3] = ld32(ftile + base01 + ic + 8);
                aHi[1][0] = ld32(ftile + base10 + ic);
                aHi[1][1] = ld32(ftile + base11 + ic);
                aHi[1][2] = ld32(ftile + base10 + ic + 8);
                aHi[1][3] = ld32(ftile + base11 + ic + 8);
#pragma unroll
                for (int nb = 0; nb < 8; nb++) {
                    int n = nh * 64 + nb * 8 + g;
                    uint4 w = wt[n][skh * 4 + sk][t];
#pragma unroll
                    for (int f = 0; f < 2; f++) {
                        mma16816(d[f][nb], aHi[f], w.x, w.y);
                        mma16816(d[f][nb], aHi[f], w.z, w.w);
                    }
                }
            }
        }
        __syncthreads();
    }

    // 2-pass epilogue: bias+relu into smem (reuse ftile), column sums, atomic.
    float* s = (float*)ftile;
    int col = tid & 63;
    int q = tid >> 6;
    float csum = 0.f;
#pragma unroll
    for (int f = 0; f < 2; f++) {
#pragma unroll
        for (int nb = 0; nb < 8; nb++) {
            int c = nb * 8 + cbase;
            float b0 = bias[nh * 64 + c];
            float b1 = bias[nh * 64 + c + 1];
            s[xx0 * 65 + c]     = fmaxf(d[f][nb][0] + b0, 0.f);
            s[xx0 * 65 + c + 1] = fmaxf(d[f][nb][1] + b1, 0.f);
            s[xx1 * 65 + c]     = fmaxf(d[f][nb][2] + b0, 0.f);
            s[xx1 * 65 + c + 1] = fmaxf(d[f][nb][3] + b1, 0.f);
        }
        __syncthreads();
        for (int r = q * 32; r < q * 32 + 32; r++) csum += s[r * 65 + col];
        __syncthreads();
    }
    atomicAdd(&g_mean[b * 128 + nh * 64 + col], csum);
}

// ======================= head: det 1x1 + sigmoid + NMS =====================
__global__ void head_kernel(const float* __restrict__ det_w,
                            const float* __restrict__ det_b,
                            float* __restrict__ out) {
    int b = blockIdx.x;
    int lane = threadIdx.x;
    __shared__ float pv[18];
    if (lane < 18) {
        float acc = det_b[lane];
        for (int c = 0; c < 128; c++)
            acc = fmaf(det_w[lane * 128 + c], g_mean[b * 128 + c] * (1.f / 16384.f), acc);
        pv[lane] = acc;
    }
    __syncthreads();
    if (lane != 0) return;

    for (int i = 0; i < 18; i++) out[b * 18 + i] = pv[i];

    float bx[3][4], sc[3], eff[3];
    bool conf[3];
    for (int a = 0; a < 3; a++) {
        for (int k = 0; k < 4; k++) bx[a][k] = pv[a * 6 + k];
        sc[a] = 1.f / (1.f + expf(-pv[a * 6 + 4]));
        conf[a] = sc[a] > 0.5f;
        eff[a] = conf[a] ? sc[a] : -INFINITY;
    }
    int order[3];
    bool used[3] = {false, false, false};
    for (int i = 0; i < 3; i++) {
        int best = -1;
        for (int a = 0; a < 3; a++)
            if (!used[a] && (best < 0 || eff[a] > eff[best])) best = a;
        order[i] = best;
        used[best] = true;
    }
    float ox1[3], oy1[3], ox2[3], oy2[3], area[3];
    for (int i = 0; i < 3; i++) {
        int a = order[i];
        ox1[i] = bx[a][0]; oy1[i] = bx[a][1]; ox2[i] = bx[a][2]; oy2[i] = bx[a][3];
        area[i] = (ox2[i] - ox1[i]) * (oy2[i] - oy1[i]);
    }
    bool keep_s[3];
    bool sup[3] = {false, false, false};
    for (int i = 0; i < 3; i++) {
        bool valid = !sup[i];
        keep_s[i] = valid;
        if (valid) {
            for (int j = i + 1; j < 3; j++) {
                float ix1 = fmaxf(ox1[i], ox1[j]);
                float iy1 = fmaxf(oy1[i], oy1[j]);
                float ix2 = fminf(ox2[i], ox2[j]);
                float iy2 = fminf(oy2[i], oy2[j]);
                float inter = fmaxf(ix2 - ix1, 0.f) * fmaxf(iy2 - iy1, 0.f);
                float iou = inter / (area[i] + area[j] - inter);
                if (iou > 0.5f) sup[j] = true;
            }
        }
    }
    bool kp[3];
    for (int i = 0; i < 3; i++) kp[order[i]] = keep_s[i];
    for (int a = 0; a < 3; a++) kp[a] = kp[a] && conf[a];

    for (int a = 0; a < 3; a++) {
        for (int k = 0; k < 4; k++) out[144 + b * 12 + a * 4 + k] = bx[a][k];
        out[240 + b * 3 + a] = sc[a];
        out[264 + b * 3 + a] = kp[a] ? 1.f : 0.f;
    }
}

// ===========================================================================
extern "C" void kernel_launch(void* const* d_in, const int* in_sizes, int n_in,
                              void* d_out, int out_size) {
    const float* x      = (const float*)d_in[0];
    const float* rgb_w1 = (const float*)d_in[1];
    const float* rgb_b1 = (const float*)d_in[2];
    const float* rgb_w2 = (const float*)d_in[3];
    const float* rgb_b2 = (const float*)d_in[4];
    const float* ir_w1  = (const float*)d_in[5];
    const float* ir_b1  = (const float*)d_in[6];
    const float* ir_w2  = (const float*)d_in[7];
    const float* ir_b2  = (const float*)d_in[8];
    const float* fuse_w = (const float*)d_in[9];
    const float* fuse_b = (const float*)d_in[10];
    const float* det_w  = (const float*)d_in[11];
    const float* det_b  = (const float*)d_in[12];
    float* out = (float*)d_out;

    cudaFuncSetAttribute(fuse_mma, cudaFuncAttributeMaxDynamicSharedMemorySize, FUSE_SMEM);

    zero_mean_kernel<<<1, 1024>>>();
    halo_p1_kernel<<<(BATCH * 1028 * 32 + 255) / 256, 256>>>();
    halo_cc_kernel<<<(BATCH * 516 * 128 + 255) / 256, 256>>>();
    xform_w1<<<2, 256>>>(rgb_w1, ir_w1);
    xform_w2<<<18, 256>>>(rgb_w2, 0);
    xform_w2<<<18, 256>>>(ir_w2, 1);
    xform_wf<<<144, 256>>>(fuse_w);

    conv1_mma<<<8192, 256>>>(x, rgb_b1, ir_b1);
    conv2_mma<<<4096, 256>>>(rgb_b2, ir_b2);
    fuse_mma<<<1024, 256, FUSE_SMEM>>>(fuse_b);
    head_kernel<<<8, 32>>>(det_w, det_b, out);
}

// round 16
// speedup vs baseline: 1.6039x; 1.6039x over previous
#include <cuda_runtime.h>
#include <cuda_bf16.h>
#include <stdint.h>
#include <math.h>

#define BATCH 8
#define H0 512

typedef unsigned short u16;

// ------------------------- scratch globals (no allocs) ---------------------
// pool1 per stream, halo-padded channel-last bf16: [b][258][258][32]
#define P1W 258
#define NP1 ((size_t)BATCH * P1W * P1W * 32)
__device__ u16 g_p1[2][NP1];
// concat halo-padded channel-last bf16: [b][130][130][128]
#define CCW 130
#define NCC ((size_t)BATCH * CCW * CCW * 128)
__device__ u16 g_cc[NCC];
__device__ float g_mean[BATCH * 128];

// pre-packed weights as uint4 {bhi0, bhi1, blo0, blo1}: [...][oc][sk][t]
__device__ uint4 g_wc1[64][2][4];
__device__ uint4 g_wc2[18][64][2][4];
__device__ uint4 g_wf[9][128][8][4];

// ------------------------- numeric helpers ---------------------------------
__device__ __forceinline__ u16 bf_hi(float v) {
    return __bfloat16_as_ushort(__float2bfloat16(v));
}
__device__ __forceinline__ u16 bf_lo(float v) {
    float h = __bfloat162float(__float2bfloat16(v));
    return __bfloat16_as_ushort(__float2bfloat16(v - h));
}
__device__ __forceinline__ uint32_t pack_hi2(float v0, float v1) {
    return (uint32_t)bf_hi(v0) | ((uint32_t)bf_hi(v1) << 16);
}
__device__ __forceinline__ uint32_t pack_lo2(float v0, float v1) {
    return (uint32_t)bf_lo(v0) | ((uint32_t)bf_lo(v1) << 16);
}

// m16n8k16 bf16 HMMA, D += A*B (fp32 accumulate)
__device__ __forceinline__ void mma16816(float* d, const uint32_t* a, uint32_t b0, uint32_t b1) {
    asm volatile(
        "mma.sync.aligned.m16n8k16.row.col.f32.bf16.bf16.f32 "
        "{%0,%1,%2,%3}, {%4,%5,%6,%7}, {%8,%9}, {%0,%1,%2,%3};"
        : "+f"(d[0]), "+f"(d[1]), "+f"(d[2]), "+f"(d[3])
        : "r"(a[0]), "r"(a[1]), "r"(a[2]), "r"(a[3]), "r"(b0), "r"(b1));
}

__device__ __forceinline__ uint32_t ld32(const u16* p) {
    return *(const uint32_t*)p;
}

// ------------------------- prep: mean + halos (one kernel) -----------------
#define N_T0 (BATCH * 128)
#define N_T1 (BATCH * 1028 * 32)
#define N_T2 (BATCH * 516 * 128)
#define N_PREP (N_T0 + N_T1 + N_T2)

__global__ void prep_kernel() {
    int idx = blockIdx.x * 256 + threadIdx.x;
    if (idx < N_T0) {                               // zero g_mean
        g_mean[idx] = 0.f;
        return;
    }
    idx -= N_T0;
    if (idx < N_T1) {                               // pool1 halo ring
        int c = idx & 31;
        int r = idx >> 5;
        int b = r / 1028;
        int p = r - b * 1028;
        int y, x;
        if (p < 258)      { y = 0;           x = p; }
        else if (p < 516) { y = 257;         x = p - 258; }
        else if (p < 772) { y = p - 516 + 1; x = 0; }
        else              { y = p - 772 + 1; x = 257; }
        size_t i = (((size_t)(b * P1W + y)) * P1W + x) * 32 + c;
        g_p1[0][i] = 0;
        g_p1[1][i] = 0;
        return;
    }
    idx -= N_T1;
    if (idx < N_T2) {                               // concat halo ring
        int c = idx & 127;
        int r = idx >> 7;
        int b = r / 516;
        int p = r - b * 516;
        int y, x;
        if (p < 130)      { y = 0;           x = p; }
        else if (p < 260) { y = 129;         x = p - 130; }
        else if (p < 388) { y = p - 260 + 1; x = 0; }
        else              { y = p - 388 + 1; x = 129; }
        g_cc[(((size_t)(b * CCW + y)) * CCW + x) * 128 + c] = 0;
    }
}

// ------------------------- weight transforms (one kernel) ------------------
__device__ __forceinline__ float w1elem(const float* w, int ocl, int kk) {
    if (kk >= 27) return 0.f;
    int tap = kk / 3;
    int ic = kk - 3 * tap;
    return w[ocl * 27 + ic * 9 + tap];
}

#define N_XF (512 + 2 * 4608 + 9 * 4096)

__global__ void xform_kernel(const float* __restrict__ wr1, const float* __restrict__ wi1,
                             const float* __restrict__ wr2, const float* __restrict__ wi2,
                             const float* __restrict__ wf) {
    int idx = blockIdx.x * 256 + threadIdx.x;
    if (idx < 512) {                                // conv1 weights
        int oc = idx >> 3, sk = (idx >> 2) & 1, t = idx & 3;
        const float* w = (oc < 32) ? wr1 : wi1;
        int ocl = oc & 31;
        int pA = t + 8 * sk, pB = pA + 4;
        float a0 = w1elem(w, ocl, 2 * pA), a1 = w1elem(w, ocl, 2 * pA + 1);
        float b0 = w1elem(w, ocl, 2 * pB), b1 = w1elem(w, ocl, 2 * pB + 1);
        g_wc1[oc][sk][t] = make_uint4(pack_hi2(a0, a1), pack_hi2(b0, b1),
                                      pack_lo2(a0, a1), pack_lo2(b0, b1));
        return;
    }
    idx -= 512;
    if (idx < 2 * 4608) {                           // conv2 weights (both streams)
        int sidx = idx / 4608;
        int r2 = idx - sidx * 4608;
        int tap = r2 / 512;
        int rem = r2 & 511;
        int oc = rem >> 3, sk = (rem >> 2) & 1, t = rem & 3;
        const float* w = sidx ? wi2 : wr2;
        int pA = t + 8 * sk, pB = pA + 4;
        float a0 = w[oc * 288 + (2 * pA) * 9 + tap], a1 = w[oc * 288 + (2 * pA + 1) * 9 + tap];
        float b0 = w[oc * 288 + (2 * pB) * 9 + tap], b1 = w[oc * 288 + (2 * pB + 1) * 9 + tap];
        g_wc2[sidx * 9 + tap][oc][sk][t] = make_uint4(pack_hi2(a0, a1), pack_hi2(b0, b1),
                                                      pack_lo2(a0, a1), pack_lo2(b0, b1));
        return;
    }
    idx -= 2 * 4608;
    if (idx < 9 * 4096) {                           // fuse weights
        int tap = idx >> 12;
        int rem = idx & 4095;
        int oc = rem >> 5, sk = (rem >> 2) & 7, t = rem & 3;
        int pA = t + 8 * sk, pB = pA + 4;
        float a0 = wf[(oc * 128 + 2 * pA) * 9 + tap], a1 = wf[(oc * 128 + 2 * pA + 1) * 9 + tap];
        float b0 = wf[(oc * 128 + 2 * pB) * 9 + tap], b1 = wf[(oc * 128 + 2 * pB + 1) * 9 + tap];
        g_wf[tap][oc][sk][t] = make_uint4(pack_hi2(a0, a1), pack_hi2(b0, b1),
                                          pack_lo2(a0, a1), pack_lo2(b0, b1));
    }
}

// ======================= conv1 (both streams in one GEMM) ==================
__device__ __forceinline__ float conv1_fetch(const float* xb, int kk, int py, int px) {
    if (kk >= 27) return 0.f;
    int tap = kk / 3;
    int ic = kk - tap * 3;
    int kh = tap / 3;
    int kw = tap - kh * 3;
    int gy = py + kh - 1;
    int gx = px + kw - 1;
    if (gy < 0 || gy >= H0 || gx < 0 || gx >= H0) return 0.f;
    return xb[(size_t)ic * H0 * H0 + (size_t)gy * H0 + gx];
}

// grid 8192: (b, pooled row Y 0..255, x-group of 128 pre-pool cols).
// M=256 (2 dy frags x 128 xx), N=64, K=32 (27 used). A bf16-hi only.
__global__ void __launch_bounds__(256, 2)
conv1_mma(const float* __restrict__ x,
          const float* __restrict__ b_rgb,
          const float* __restrict__ b_ir) {
    __shared__ float s[128 * 65];
    int tid = threadIdx.x;
    int wid = tid >> 5;
    int lane = tid & 31;
    int g = lane >> 2;
    int t = lane & 3;
    int cbase = 2 * t;
    int bid = blockIdx.x;
    int x0 = (bid & 3) * 128;
    int Y = (bid >> 2) & 255;
    int b = bid >> 10;
    const float* xb = x + (size_t)b * 3 * H0 * H0;

    int xx0 = wid * 16 + g;
    int xx1 = xx0 + 8;

    float d[2][8][4];
#pragma unroll
    for (int f = 0; f < 2; f++)
#pragma unroll
        for (int nb = 0; nb < 8; nb++)
#pragma unroll
            for (int i = 0; i < 4; i++) d[f][nb][i] = 0.f;

#pragma unroll
    for (int sk = 0; sk < 2; sk++) {
        int k0 = sk * 16 + cbase;
        uint32_t aHi[2][4];
#pragma unroll
        for (int f = 0; f < 2; f++) {
            int py = 2 * Y + f;
            float v00 = conv1_fetch(xb, k0,     py, x0 + xx0);
            float v01 = conv1_fetch(xb, k0 + 1, py, x0 + xx0);
            float v08 = conv1_fetch(xb, k0 + 8, py, x0 + xx0);
            float v09 = conv1_fetch(xb, k0 + 9, py, x0 + xx0);
            float v10 = conv1_fetch(xb, k0,     py, x0 + xx1);
            float v11 = conv1_fetch(xb, k0 + 1, py, x0 + xx1);
            float v18 = conv1_fetch(xb, k0 + 8, py, x0 + xx1);
            float v19 = conv1_fetch(xb, k0 + 9, py, x0 + xx1);
            aHi[f][0] = pack_hi2(v00, v01);
            aHi[f][1] = pack_hi2(v10, v11);
            aHi[f][2] = pack_hi2(v08, v09);
            aHi[f][3] = pack_hi2(v18, v19);
        }
#pragma unroll
        for (int nb = 0; nb < 8; nb++) {
            int n = nb * 8 + g;
            uint4 w = g_wc1[n][sk][t];
#pragma unroll
            for (int f = 0; f < 2; f++) {
                mma16816(d[f][nb], aHi[f], w.x, w.y);
                mma16816(d[f][nb], aHi[f], w.z, w.w);
            }
        }
    }

    // 2-pass epilogue: pass f writes frag f rows (xx), pool across passes.
    float pm[16];
#pragma unroll
    for (int f = 0; f < 2; f++) {
#pragma unroll
        for (int nb = 0; nb < 8; nb++) {
            int c = nb * 8 + cbase;
            s[xx0 * 65 + c]     = d[f][nb][0];
            s[xx0 * 65 + c + 1] = d[f][nb][1];
            s[xx1 * 65 + c]     = d[f][nb][2];
            s[xx1 * 65 + c + 1] = d[f][nb][3];
        }
        __syncthreads();
#pragma unroll
        for (int k = 0; k < 16; k++) {
            int oi = k * 256 + tid;
            int oc = oi & 63;
            int j = oi >> 6;
            float m = fmaxf(s[(2 * j) * 65 + oc], s[(2 * j + 1) * 65 + oc]);
            if (f == 0) {
                pm[k] = m;
            } else {
                int st = oc >> 5;
                int ocl = oc & 31;
                float bi = st ? b_ir[ocl] : b_rgb[ocl];
                float v = fmaxf(fmaxf(pm[k], m) + bi, 0.f);
                size_t pix = (((size_t)(b * P1W + Y + 1)) * P1W + (x0 >> 1) + j + 1) * 32 + ocl;
                g_p1[st][pix] = bf_hi(v);
            }
        }
        __syncthreads();
    }
}

// ======================= conv2 (both streams, one launch) ==================
// grid 4096: (which, b, pooled row Y 0..127, x-group of 128 pre-pool cols).
// M=256, N=64 oc, K = 9 taps x 32 ic. A staged in smem (conflict-free).
#define TPX 40                                     // u16 per pixel slot (80B)
__global__ void __launch_bounds__(256, 2)
conv2_mma(const float* __restrict__ bias_r, const float* __restrict__ bias_i) {
    __shared__ u16 tile[4 * 132 * TPX];            // 42240 B
    int tid = threadIdx.x;
    int wid = tid >> 5;
    int lane = tid & 31;
    int g = lane >> 2;
    int t = lane & 3;
    int cbase = 2 * t;
    int bid = blockIdx.x;
    int x0 = (bid & 1) * 128;
    int Y = (bid >> 1) & 127;
    int b = (bid >> 8) & 7;
    int which = bid >> 11;
    const u16* ph = g_p1[which];
    const float* bias = which ? bias_i : bias_r;
    int ch_off = which * 64;
    int wm0 = which * 9;

    int xx0 = wid * 16 + g;
    int xx1 = xx0 + 8;

    // stage: rows (2Y+r), r=0..3; px x0..x0+129; all 32 ch. 2080 uint4.
    {
        const u16* src = ph + (((size_t)(b * P1W + 2 * Y)) * P1W + x0) * 32;
#pragma unroll
        for (int i = tid; i < 2080; i += 256) {
            int r = i / 520;
            int j = i - r * 520;
            int p = j >> 2;
            int q = j & 3;
            uint4 v = *(const uint4*)(src + ((size_t)r * P1W + p) * 32 + q * 8);
            *(uint4*)&tile[(r * 132 + p) * TPX + q * 8] = v;
        }
    }
    __syncthreads();

    float d[2][8][4];
#pragma unroll
    for (int f = 0; f < 2; f++)
#pragma unroll
        for (int nb = 0; nb < 8; nb++)
#pragma unroll
            for (int i = 0; i < 4; i++) d[f][nb][i] = 0.f;

#pragma unroll
    for (int tap = 0; tap < 9; tap++) {
        const int kh = tap / 3;
        const int kw = tap - kh * 3;
        const uint4(*wt)[2][4] = g_wc2[wm0 + tap];
        int base00 = ((0 + kh) * 132 + xx0 + kw) * TPX;
        int base01 = ((0 + kh) * 132 + xx1 + kw) * TPX;
        int base10 = ((1 + kh) * 132 + xx0 + kw) * TPX;
        int base11 = ((1 + kh) * 132 + xx1 + kw) * TPX;
#pragma unroll
        for (int sk = 0; sk < 2; sk++) {
            int ic = sk * 16 + cbase;
            uint32_t aHi[2][4];
            aHi[0][0] = ld32(tile + base00 + ic);
            aHi[0][1] = ld32(tile + base01 + ic);
            aHi[0][2] = ld32(tile + base00 + ic + 8);
            aHi[0][3] = ld32(tile + base01 + ic + 8);
            aHi[1][0] = ld32(tile + base10 + ic);
            aHi[1][1] = ld32(tile + base11 + ic);
            aHi[1][2] = ld32(tile + base10 + ic + 8);
            aHi[1][3] = ld32(tile + base11 + ic + 8);
#pragma unroll
            for (int nb = 0; nb < 8; nb++) {
                int n = nb * 8 + g;
                uint4 w = wt[n][sk][t];
#pragma unroll
                for (int f = 0; f < 2; f++) {
                    mma16816(d[f][nb], aHi[f], w.x, w.y);
                    mma16816(d[f][nb], aHi[f], w.z, w.w);
                }
            }
        }
    }

    // epilogue reuses tile as f32 buffer (33 KB <= 42.2 KB)
    __syncthreads();
    float* s = (float*)tile;
    float pm[16];
#pragma unroll
    for (int f = 0; f < 2; f++) {
#pragma unroll
        for (int nb = 0; nb < 8; nb++) {
            int c = nb * 8 + cbase;
            s[xx0 * 65 + c]     = d[f][nb][0];
            s[xx0 * 65 + c + 1] = d[f][nb][1];
            s[xx1 * 65 + c]     = d[f][nb][2];
            s[xx1 * 65 + c + 1] = d[f][nb][3];
        }
        __syncthreads();
#pragma unroll
        for (int k = 0; k < 16; k++) {
            int oi = k * 256 + tid;
            int oc = oi & 63;
            int j = oi >> 6;
            float m = fmaxf(s[(2 * j) * 65 + oc], s[(2 * j + 1) * 65 + oc]);
            if (f == 0) {
                pm[k] = m;
            } else {
                float v = fmaxf(fmaxf(pm[k], m) + bias[oc], 0.f);
                size_t pix = (((size_t)(b * CCW + Y + 1)) * CCW + (x0 >> 1) + j + 1) * 128 + ch_off + oc;
                g_cc[pix] = bf_hi(v);
            }
        }
        __syncthreads();
    }
}

// ======================= fuse (128->128 conv + relu + mean) ================
// grid 1024: (b, y-pair 0..63, oc-half). M=256 (2 y rows x 128 x), N=64,
// K = 9 taps x 128 ic. Padded + unrolled global loads (R12/R14 form).
__global__ void __launch_bounds__(256, 2)
fuse_mma(const float* __restrict__ bias) {
    __shared__ float s[128 * 65];
    int tid = threadIdx.x;
    int wid = tid >> 5;
    int lane = tid & 31;
    int g = lane >> 2;
    int t = lane & 3;
    int cbase = 2 * t;
    int bid = blockIdx.x;
    int nh = bid & 1;
    int yp = (bid >> 1) & 63;
    int b = bid >> 7;
    int y0 = 2 * yp;

    int xx0 = wid * 16 + g;
    int xx1 = xx0 + 8;

    size_t pb[2][2];
#pragma unroll
    for (int f = 0; f < 2; f++) {
        pb[f][0] = (((size_t)(b * CCW + y0 + f + 1)) * CCW + (xx0 + 1)) * 128;
        pb[f][1] = (((size_t)(b * CCW + y0 + f + 1)) * CCW + (xx1 + 1)) * 128;
    }

    float d[2][8][4];
#pragma unroll
    for (int f = 0; f < 2; f++)
#pragma unroll
        for (int nb = 0; nb < 8; nb++)
#pragma unroll
            for (int i = 0; i < 4; i++) d[f][nb][i] = 0.f;

#pragma unroll
    for (int tap = 0; tap < 9; tap++) {
        const int kh = tap / 3;
        const int kw = tap - kh * 3;
        const ptrdiff_t to = ((ptrdiff_t)(kh - 1) * CCW + (kw - 1)) * 128;
        const uint4(*wt)[8][4] = g_wf[tap];
#pragma unroll
        for (int sk = 0; sk < 8; sk++) {
            int ic = sk * 16 + cbase;
            uint32_t aHi[2][4];
#pragma unroll
            for (int f = 0; f < 2; f++) {
                aHi[f][0] = ld32(g_cc + pb[f][0] + to + ic);
                aHi[f][1] = ld32(g_cc + pb[f][1] + to + ic);
                aHi[f][2] = ld32(g_cc + pb[f][0] + to + ic + 8);
                aHi[f][3] = ld32(g_cc + pb[f][1] + to + ic + 8);
            }
#pragma unroll
            for (int nb = 0; nb < 8; nb++) {
                int n = nh * 64 + nb * 8 + g;
                uint4 w = wt[n][sk][t];
#pragma unroll
                for (int f = 0; f < 2; f++) {
                    mma16816(d[f][nb], aHi[f], w.x, w.y);
                    mma16816(d[f][nb], aHi[f], w.z, w.w);
                }
            }
        }
    }

    // 2-pass epilogue: bias+relu into smem, column partial sums, atomic mean.
    int col = tid & 63;
    int q = tid >> 6;
    float csum = 0.f;
#pragma unroll
    for (int f = 0; f < 2; f++) {
#pragma unroll
        for (int nb = 0; nb < 8; nb++) {
            int c = nb * 8 + cbase;
            float b0 = bias[nh * 64 + c];
            float b1 = bias[nh * 64 + c + 1];
            s[xx0 * 65 + c]     = fmaxf(d[f][nb][0] + b0, 0.f);
            s[xx0 * 65 + c + 1] = fmaxf(d[f][nb][1] + b1, 0.f);
            s[xx1 * 65 + c]     = fmaxf(d[f][nb][2] + b0, 0.f);
            s[xx1 * 65 + c + 1] = fmaxf(d[f][nb][3] + b1, 0.f);
        }
        __syncthreads();
        for (int r = q * 32; r < q * 32 + 32; r++) csum += s[r * 65 + col];
        __syncthreads();
    }
    atomicAdd(&g_mean[b * 128 + nh * 64 + col], csum);
}

// ======================= head: det 1x1 + sigmoid + NMS =====================
__global__ void head_kernel(const float* __restrict__ det_w,
                            const float* __restrict__ det_b,
                            float* __restrict__ out) {
    int b = blockIdx.x;
    int lane = threadIdx.x;
    __shared__ float pv[18];
    if (lane < 18) {
        float acc = det_b[lane];
        for (int c = 0; c < 128; c++)
            acc = fmaf(det_w[lane * 128 + c], g_mean[b * 128 + c] * (1.f / 16384.f), acc);
        pv[lane] = acc;
    }
    __syncthreads();
    if (lane != 0) return;

    for (int i = 0; i < 18; i++) out[b * 18 + i] = pv[i];

    float bx[3][4], sc[3], eff[3];
    bool conf[3];
    for (int a = 0; a < 3; a++) {
        for (int k = 0; k < 4; k++) bx[a][k] = pv[a * 6 + k];
        sc[a] = 1.f / (1.f + expf(-pv[a * 6 + 4]));
        conf[a] = sc[a] > 0.5f;
        eff[a] = conf[a] ? sc[a] : -INFINITY;
    }
    int order[3];
    bool used[3] = {false, false, false};
    for (int i = 0; i < 3; i++) {
        int best = -1;
        for (int a = 0; a < 3; a++)
            if (!used[a] && (best < 0 || eff[a] > eff[best])) best = a;
        order[i] = best;
        used[best] = true;
    }
    float ox1[3], oy1[3], ox2[3], oy2[3], area[3];
    for (int i = 0; i < 3; i++) {
        int a = order[i];
        ox1[i] = bx[a][0]; oy1[i] = bx[a][1]; ox2[i] = bx[a][2]; oy2[i] = bx[a][3];
        area[i] = (ox2[i] - ox1[i]) * (oy2[i] - oy1[i]);
    }
    bool keep_s[3];
    bool sup[3] = {false, false, false};
    for (int i = 0; i < 3; i++) {
        bool valid = !sup[i];
        keep_s[i] = valid;
        if (valid) {
            for (int j = i + 1; j < 3; j++) {
                float ix1 = fmaxf(ox1[i], ox1[j]);
                float iy1 = fmaxf(oy1[i], oy1[j]);
                float ix2 = fminf(ox2[i], ox2[j]);
                float iy2 = fminf(oy2[i], oy2[j]);
                float inter = fmaxf(ix2 - ix1, 0.f) * fmaxf(iy2 - iy1, 0.f);
                float iou = inter / (area[i] + area[j] - inter);
                if (iou > 0.5f) sup[j] = true;
            }
        }
    }
    bool kp[3];
    for (int i = 0; i < 3; i++) kp[order[i]] = keep_s[i];
    for (int a = 0; a < 3; a++) kp[a] = kp[a] && conf[a];

    for (int a = 0; a < 3; a++) {
        for (int k = 0; k < 4; k++) out[144 + b * 12 + a * 4 + k] = bx[a][k];
        out[240 + b * 3 + a] = sc[a];
        out[264 + b * 3 + a] = kp[a] ? 1.f : 0.f;
    }
}

// ===========================================================================
extern "C" void kernel_launch(void* const* d_in, const int* in_sizes, int n_in,
                              void* d_out, int out_size) {
    const float* x      = (const float*)d_in[0];
    const float* rgb_w1 = (const float*)d_in[1];
    const float* rgb_b1 = (const float*)d_in[2];
    const float* rgb_w2 = (const float*)d_in[3];
    const float* rgb_b2 = (const float*)d_in[4];
    const float* ir_w1  = (const float*)d_in[5];
    const float* ir_b1  = (const float*)d_in[6];
    const float* ir_w2  = (const float*)d_in[7];
    const float* ir_b2  = (const float*)d_in[8];
    const float* fuse_w = (const float*)d_in[9];
    const float* fuse_b = (const float*)d_in[10];
    const float* det_w  = (const float*)d_in[11];
    const float* det_b  = (const float*)d_in[12];
    float* out = (float*)d_out;

    prep_kernel<<<(N_PREP + 255) / 256, 256>>>();
    xform_kernel<<<(N_XF + 255) / 256, 256>>>(rgb_w1, ir_w1, rgb_w2, ir_w2, fuse_w);

    conv1_mma<<<8192, 256>>>(x, rgb_b1, ir_b1);
    conv2_mma<<<4096, 256>>>(rgb_b2, ir_b2);
    fuse_mma<<<1024, 256>>>(fuse_b);
    head_kernel<<<8, 32>>>(det_w, det_b, out);
}

// round 17
// speedup vs baseline: 1.8596x; 1.1594x over previous
#include <cuda_runtime.h>
#include <cuda_bf16.h>
#include <stdint.h>
#include <math.h>

#define BATCH 8
#define H0 512

typedef unsigned short u16;

// ------------------------- scratch globals (no allocs) ---------------------
// pool1 per stream, halo-padded channel-last bf16: [b][258][258][32]
#define P1W 258
#define NP1 ((size_t)BATCH * P1W * P1W * 32)
__device__ u16 g_p1[2][NP1];
// concat halo-padded channel-last bf16: [b][130][130][128]
#define CCW 130
#define NCC ((size_t)BATCH * CCW * CCW * 128)
__device__ u16 g_cc[NCC];
__device__ float g_mean[BATCH * 128];

// pre-packed weights as uint4 {bhi0, bhi1, blo0, blo1}.
// Layout [..][sk][oc][t]: one warp's (8 oc x 4 t) B read is 512B contiguous.
__device__ uint4 g_wc1[2][64][4];
__device__ uint4 g_wc2[18][2][64][4];
__device__ uint4 g_wf[9][8][128][4];

// ------------------------- numeric helpers ---------------------------------
__device__ __forceinline__ u16 bf_hi(float v) {
    return __bfloat16_as_ushort(__float2bfloat16(v));
}
__device__ __forceinline__ u16 bf_lo(float v) {
    float h = __bfloat162float(__float2bfloat16(v));
    return __bfloat16_as_ushort(__float2bfloat16(v - h));
}
__device__ __forceinline__ uint32_t pack_hi2(float v0, float v1) {
    return (uint32_t)bf_hi(v0) | ((uint32_t)bf_hi(v1) << 16);
}
__device__ __forceinline__ uint32_t pack_lo2(float v0, float v1) {
    return (uint32_t)bf_lo(v0) | ((uint32_t)bf_lo(v1) << 16);
}

// m16n8k16 bf16 HMMA, D += A*B (fp32 accumulate)
__device__ __forceinline__ void mma16816(float* d, const uint32_t* a, uint32_t b0, uint32_t b1) {
    asm volatile(
        "mma.sync.aligned.m16n8k16.row.col.f32.bf16.bf16.f32 "
        "{%0,%1,%2,%3}, {%4,%5,%6,%7}, {%8,%9}, {%0,%1,%2,%3};"
        : "+f"(d[0]), "+f"(d[1]), "+f"(d[2]), "+f"(d[3])
        : "r"(a[0]), "r"(a[1]), "r"(a[2]), "r"(a[3]), "r"(b0), "r"(b1));
}

__device__ __forceinline__ uint32_t ld32(const u16* p) {
    return *(const uint32_t*)p;
}

// ------------------------- prep: mean + halos (one kernel) -----------------
#define N_T0 (BATCH * 128)
#define N_T1 (BATCH * 1028 * 32)
#define N_T2 (BATCH * 516 * 128)
#define N_PREP (N_T0 + N_T1 + N_T2)

__global__ void prep_kernel() {
    int idx = blockIdx.x * 256 + threadIdx.x;
    if (idx < N_T0) {                               // zero g_mean
        g_mean[idx] = 0.f;
        return;
    }
    idx -= N_T0;
    if (idx < N_T1) {                               // pool1 halo ring
        int c = idx & 31;
        int r = idx >> 5;
        int b = r / 1028;
        int p = r - b * 1028;
        int y, x;
        if (p < 258)      { y = 0;           x = p; }
        else if (p < 516) { y = 257;         x = p - 258; }
        else if (p < 772) { y = p - 516 + 1; x = 0; }
        else              { y = p - 772 + 1; x = 257; }
        size_t i = (((size_t)(b * P1W + y)) * P1W + x) * 32 + c;
        g_p1[0][i] = 0;
        g_p1[1][i] = 0;
        return;
    }
    idx -= N_T1;
    if (idx < N_T2) {                               // concat halo ring
        int c = idx & 127;
        int r = idx >> 7;
        int b = r / 516;
        int p = r - b * 516;
        int y, x;
        if (p < 130)      { y = 0;           x = p; }
        else if (p < 260) { y = 129;         x = p - 130; }
        else if (p < 388) { y = p - 260 + 1; x = 0; }
        else              { y = p - 388 + 1; x = 129; }
        g_cc[(((size_t)(b * CCW + y)) * CCW + x) * 128 + c] = 0;
    }
}

// ------------------------- weight transforms (one kernel) ------------------
__device__ __forceinline__ float w1elem(const float* w, int ocl, int kk) {
    if (kk >= 27) return 0.f;
    int tap = kk / 3;
    int ic = kk - 3 * tap;
    return w[ocl * 27 + ic * 9 + tap];
}

#define N_XF (512 + 2 * 4608 + 9 * 4096)

__global__ void xform_kernel(const float* __restrict__ wr1, const float* __restrict__ wi1,
                             const float* __restrict__ wr2, const float* __restrict__ wi2,
                             const float* __restrict__ wf) {
    int idx = blockIdx.x * 256 + threadIdx.x;
    if (idx < 512) {                                // conv1 weights
        int oc = idx >> 3, sk = (idx >> 2) & 1, t = idx & 3;
        const float* w = (oc < 32) ? wr1 : wi1;
        int ocl = oc & 31;
        int pA = t + 8 * sk, pB = pA + 4;
        float a0 = w1elem(w, ocl, 2 * pA), a1 = w1elem(w, ocl, 2 * pA + 1);
        float b0 = w1elem(w, ocl, 2 * pB), b1 = w1elem(w, ocl, 2 * pB + 1);
        g_wc1[sk][oc][t] = make_uint4(pack_hi2(a0, a1), pack_hi2(b0, b1),
                                      pack_lo2(a0, a1), pack_lo2(b0, b1));
        return;
    }
    idx -= 512;
    if (idx < 2 * 4608) {                           // conv2 weights (both streams)
        int sidx = idx / 4608;
        int r2 = idx - sidx * 4608;
        int tap = r2 / 512;
        int rem = r2 & 511;
        int oc = rem >> 3, sk = (rem >> 2) & 1, t = rem & 3;
        const float* w = sidx ? wi2 : wr2;
        int pA = t + 8 * sk, pB = pA + 4;
        float a0 = w[oc * 288 + (2 * pA) * 9 + tap], a1 = w[oc * 288 + (2 * pA + 1) * 9 + tap];
        float b0 = w[oc * 288 + (2 * pB) * 9 + tap], b1 = w[oc * 288 + (2 * pB + 1) * 9 + tap];
        g_wc2[sidx * 9 + tap][sk][oc][t] = make_uint4(pack_hi2(a0, a1), pack_hi2(b0, b1),
                                                      pack_lo2(a0, a1), pack_lo2(b0, b1));
        return;
    }
    idx -= 2 * 4608;
    if (idx < 9 * 4096) {                           // fuse weights
        int tap = idx >> 12;
        int rem = idx & 4095;
        int oc = rem >> 5, sk = (rem >> 2) & 7, t = rem & 3;
        int pA = t + 8 * sk, pB = pA + 4;
        float a0 = wf[(oc * 128 + 2 * pA) * 9 + tap], a1 = wf[(oc * 128 + 2 * pA + 1) * 9 + tap];
        float b0 = wf[(oc * 128 + 2 * pB) * 9 + tap], b1 = wf[(oc * 128 + 2 * pB + 1) * 9 + tap];
        g_wf[tap][sk][oc][t] = make_uint4(pack_hi2(a0, a1), pack_hi2(b0, b1),
                                          pack_lo2(a0, a1), pack_lo2(b0, b1));
    }
}

// ======================= conv1 (both streams in one GEMM) ==================
__device__ __forceinline__ float conv1_fetch(const float* xb, int kk, int py, int px) {
    if (kk >= 27) return 0.f;
    int tap = kk / 3;
    int ic = kk - tap * 3;
    int kh = tap / 3;
    int kw = tap - kh * 3;
    int gy = py + kh - 1;
    int gx = px + kw - 1;
    if (gy < 0 || gy >= H0 || gx < 0 || gx >= H0) return 0.f;
    return xb[(size_t)ic * H0 * H0 + (size_t)gy * H0 + gx];
}

// grid 8192: (b, pooled row Y 0..255, x-group of 128 pre-pool cols).
// M=256 (2 dy frags x 128 xx), N=64, K=32 (27 used). A bf16-hi only.
__global__ void __launch_bounds__(256, 2)
conv1_mma(const float* __restrict__ x,
          const float* __restrict__ b_rgb,
          const float* __restrict__ b_ir) {
    __shared__ float s[128 * 65];
    int tid = threadIdx.x;
    int wid = tid >> 5;
    int lane = tid & 31;
    int g = lane >> 2;
    int t = lane & 3;
    int cbase = 2 * t;
    int bid = blockIdx.x;
    int x0 = (bid & 3) * 128;
    int Y = (bid >> 2) & 255;
    int b = bid >> 10;
    const float* xb = x + (size_t)b * 3 * H0 * H0;

    int xx0 = wid * 16 + g;
    int xx1 = xx0 + 8;

    float d[2][8][4];
#pragma unroll
    for (int f = 0; f < 2; f++)
#pragma unroll
        for (int nb = 0; nb < 8; nb++)
#pragma unroll
            for (int i = 0; i < 4; i++) d[f][nb][i] = 0.f;

#pragma unroll
    for (int sk = 0; sk < 2; sk++) {
        int k0 = sk * 16 + cbase;
        uint32_t aHi[2][4];
#pragma unroll
        for (int f = 0; f < 2; f++) {
            int py = 2 * Y + f;
            float v00 = conv1_fetch(xb, k0,     py, x0 + xx0);
            float v01 = conv1_fetch(xb, k0 + 1, py, x0 + xx0);
            float v08 = conv1_fetch(xb, k0 + 8, py, x0 + xx0);
            float v09 = conv1_fetch(xb, k0 + 9, py, x0 + xx0);
            float v10 = conv1_fetch(xb, k0,     py, x0 + xx1);
            float v11 = conv1_fetch(xb, k0 + 1, py, x0 + xx1);
            float v18 = conv1_fetch(xb, k0 + 8, py, x0 + xx1);
            float v19 = conv1_fetch(xb, k0 + 9, py, x0 + xx1);
            aHi[f][0] = pack_hi2(v00, v01);
            aHi[f][1] = pack_hi2(v10, v11);
            aHi[f][2] = pack_hi2(v08, v09);
            aHi[f][3] = pack_hi2(v18, v19);
        }
        const uint4(*wsk)[4] = g_wc1[sk];
#pragma unroll
        for (int nb = 0; nb < 8; nb++) {
            int n = nb * 8 + g;
            uint4 w = wsk[n][t];
#pragma unroll
            for (int f = 0; f < 2; f++) {
                mma16816(d[f][nb], aHi[f], w.x, w.y);
                mma16816(d[f][nb], aHi[f], w.z, w.w);
            }
        }
    }

    // 2-pass epilogue: pass f writes frag f rows (xx), pool across passes.
    float pm[16];
#pragma unroll
    for (int f = 0; f < 2; f++) {
#pragma unroll
        for (int nb = 0; nb < 8; nb++) {
            int c = nb * 8 + cbase;
            s[xx0 * 65 + c]     = d[f][nb][0];
            s[xx0 * 65 + c + 1] = d[f][nb][1];
            s[xx1 * 65 + c]     = d[f][nb][2];
            s[xx1 * 65 + c + 1] = d[f][nb][3];
        }
        __syncthreads();
#pragma unroll
        for (int k = 0; k < 16; k++) {
            int oi = k * 256 + tid;
            int oc = oi & 63;
            int j = oi >> 6;
            float m = fmaxf(s[(2 * j) * 65 + oc], s[(2 * j + 1) * 65 + oc]);
            if (f == 0) {
                pm[k] = m;
            } else {
                int st = oc >> 5;
                int ocl = oc & 31;
                float bi = st ? b_ir[ocl] : b_rgb[ocl];
                float v = fmaxf(fmaxf(pm[k], m) + bi, 0.f);
                size_t pix = (((size_t)(b * P1W + Y + 1)) * P1W + (x0 >> 1) + j + 1) * 32 + ocl;
                g_p1[st][pix] = bf_hi(v);
            }
        }
        __syncthreads();
    }
}

// ======================= conv2 (both streams, one launch) ==================
// grid 4096: (which, b, pooled row Y 0..127, x-group of 128 pre-pool cols).
// M=256, N=64 oc, K = 9 taps x 32 ic. A staged in smem (conflict-free);
// B reads contiguous 512B per warp per (tap,sk).
#define TPX 40                                     // u16 per pixel slot (80B)
__global__ void __launch_bounds__(256, 2)
conv2_mma(const float* __restrict__ bias_r, const float* __restrict__ bias_i) {
    __shared__ u16 tile[4 * 132 * TPX];            // 42240 B
    int tid = threadIdx.x;
    int wid = tid >> 5;
    int lane = tid & 31;
    int g = lane >> 2;
    int t = lane & 3;
    int cbase = 2 * t;
    int bid = blockIdx.x;
    int x0 = (bid & 1) * 128;
    int Y = (bid >> 1) & 127;
    int b = (bid >> 8) & 7;
    int which = bid >> 11;
    const u16* ph = g_p1[which];
    const float* bias = which ? bias_i : bias_r;
    int ch_off = which * 64;
    int wm0 = which * 9;

    int xx0 = wid * 16 + g;
    int xx1 = xx0 + 8;

    // stage: rows (2Y+r), r=0..3; px x0..x0+129; all 32 ch. 2080 uint4.
    {
        const u16* src = ph + (((size_t)(b * P1W + 2 * Y)) * P1W + x0) * 32;
#pragma unroll
        for (int i = tid; i < 2080; i += 256) {
            int r = i / 520;
            int j = i - r * 520;
            int p = j >> 2;
            int q = j & 3;
            uint4 v = *(const uint4*)(src + ((size_t)r * P1W + p) * 32 + q * 8);
            *(uint4*)&tile[(r * 132 + p) * TPX + q * 8] = v;
        }
    }
    __syncthreads();

    float d[2][8][4];
#pragma unroll
    for (int f = 0; f < 2; f++)
#pragma unroll
        for (int nb = 0; nb < 8; nb++)
#pragma unroll
            for (int i = 0; i < 4; i++) d[f][nb][i] = 0.f;

#pragma unroll
    for (int tap = 0; tap < 9; tap++) {
        const int kh = tap / 3;
        const int kw = tap - kh * 3;
        int base00 = ((0 + kh) * 132 + xx0 + kw) * TPX;
        int base01 = ((0 + kh) * 132 + xx1 + kw) * TPX;
        int base10 = ((1 + kh) * 132 + xx0 + kw) * TPX;
        int base11 = ((1 + kh) * 132 + xx1 + kw) * TPX;
#pragma unroll
        for (int sk = 0; sk < 2; sk++) {
            int ic = sk * 16 + cbase;
            uint32_t aHi[2][4];
            aHi[0][0] = ld32(tile + base00 + ic);
            aHi[0][1] = ld32(tile + base01 + ic);
            aHi[0][2] = ld32(tile + base00 + ic + 8);
            aHi[0][3] = ld32(tile + base01 + ic + 8);
            aHi[1][0] = ld32(tile + base10 + ic);
            aHi[1][1] = ld32(tile + base11 + ic);
            aHi[1][2] = ld32(tile + base10 + ic + 8);
            aHi[1][3] = ld32(tile + base11 + ic + 8);
            const uint4(*wsk)[4] = g_wc2[wm0 + tap][sk];
#pragma unroll
            for (int nb = 0; nb < 8; nb++) {
                int n = nb * 8 + g;
                uint4 w = wsk[n][t];
#pragma unroll
                for (int f = 0; f < 2; f++) {
                    mma16816(d[f][nb], aHi[f], w.x, w.y);
                    mma16816(d[f][nb], aHi[f], w.z, w.w);
                }
            }
        }
    }

    // epilogue reuses tile as f32 buffer (33 KB <= 42.2 KB)
    __syncthreads();
    float* s = (float*)tile;
    float pm[16];
#pragma unroll
    for (int f = 0; f < 2; f++) {
#pragma unroll
        for (int nb = 0; nb < 8; nb++) {
            int c = nb * 8 + cbase;
            s[xx0 * 65 + c]     = d[f][nb][0];
            s[xx0 * 65 + c + 1] = d[f][nb][1];
            s[xx1 * 65 + c]     = d[f][nb][2];
            s[xx1 * 65 + c + 1] = d[f][nb][3];
        }
        __syncthreads();
#pragma unroll
        for (int k = 0; k < 16; k++) {
            int oi = k * 256 + tid;
            int oc = oi & 63;
            int j = oi >> 6;
            float m = fmaxf(s[(2 * j) * 65 + oc], s[(2 * j + 1) * 65 + oc]);
            if (f == 0) {
                pm[k] = m;
            } else {
                float v = fmaxf(fmaxf(pm[k], m) + bias[oc], 0.f);
                size_t pix = (((size_t)(b * CCW + Y + 1)) * CCW + (x0 >> 1) + j + 1) * 128 + ch_off + oc;
                g_cc[pix] = bf_hi(v);
            }
        }
        __syncthreads();
    }
}

// ======================= fuse (128->128 conv + relu + mean) ================
// grid 1024: (b, y-pair 0..63, oc-half). M=256 (2 y rows x 128 x), N=64,
// K = 9 taps x 128 ic. Padded + unrolled global A loads; contiguous B reads.
__global__ void __launch_bounds__(256, 2)
fuse_mma(const float* __restrict__ bias) {
    __shared__ float s[128 * 65];
    int tid = threadIdx.x;
    int wid = tid >> 5;
    int lane = tid & 31;
    int g = lane >> 2;
    int t = lane & 3;
    int cbase = 2 * t;
    int bid = blockIdx.x;
    int nh = bid & 1;
    int yp = (bid >> 1) & 63;
    int b = bid >> 7;
    int y0 = 2 * yp;

    int xx0 = wid * 16 + g;
    int xx1 = xx0 + 8;

    size_t pb[2][2];
#pragma unroll
    for (int f = 0; f < 2; f++) {
        pb[f][0] = (((size_t)(b * CCW + y0 + f + 1)) * CCW + (xx0 + 1)) * 128;
        pb[f][1] = (((size_t)(b * CCW + y0 + f + 1)) * CCW + (xx1 + 1)) * 128;
    }

    float d[2][8][4];
#pragma unroll
    for (int f = 0; f < 2; f++)
#pragma unroll
        for (int nb = 0; nb < 8; nb++)
#pragma unroll
            for (int i = 0; i < 4; i++) d[f][nb][i] = 0.f;

#pragma unroll
    for (int tap = 0; tap < 9; tap++) {
        const int kh = tap / 3;
        const int kw = tap - kh * 3;
        const ptrdiff_t to = ((ptrdiff_t)(kh - 1) * CCW + (kw - 1)) * 128;
#pragma unroll
        for (int sk = 0; sk < 8; sk++) {
            int ic = sk * 16 + cbase;
            uint32_t aHi[2][4];
#pragma unroll
            for (int f = 0; f < 2; f++) {
                aHi[f][0] = ld32(g_cc + pb[f][0] + to + ic);
                aHi[f][1] = ld32(g_cc + pb[f][1] + to + ic);
                aHi[f][2] = ld32(g_cc + pb[f][0] + to + ic + 8);
                aHi[f][3] = ld32(g_cc + pb[f][1] + to + ic + 8);
            }
            const uint4(*wsk)[4] = g_wf[tap][sk];
#pragma unroll
            for (int nb = 0; nb < 8; nb++) {
                int n = nh * 64 + nb * 8 + g;
                uint4 w = wsk[n][t];
#pragma unroll
                for (int f = 0; f < 2; f++) {
                    mma16816(d[f][nb], aHi[f], w.x, w.y);
                    mma16816(d[f][nb], aHi[f], w.z, w.w);
                }
            }
        }
    }

    // 2-pass epilogue: bias+relu into smem, column partial sums, atomic mean.
    int col = tid & 63;
    int q = tid >> 6;
    float csum = 0.f;
#pragma unroll
    for (int f = 0; f < 2; f++) {
#pragma unroll
        for (int nb = 0; nb < 8; nb++) {
            int c = nb * 8 + cbase;
            float b0 = bias[nh * 64 + c];
            float b1 = bias[nh * 64 + c + 1];
            s[xx0 * 65 + c]     = fmaxf(d[f][nb][0] + b0, 0.f);
            s[xx0 * 65 + c + 1] = fmaxf(d[f][nb][1] + b1, 0.f);
            s[xx1 * 65 + c]     = fmaxf(d[f][nb][2] + b0, 0.f);
            s[xx1 * 65 + c + 1] = fmaxf(d[f][nb][3] + b1, 0.f);
        }
        __syncthreads();
        for (int r = q * 32; r < q * 32 + 32; r++) csum += s[r * 65 + col];
        __syncthreads();
    }
    atomicAdd(&g_mean[b * 128 + nh * 64 + col], csum);
}

// ======================= head: det 1x1 + sigmoid + NMS =====================
__global__ void head_kernel(const float* __restrict__ det_w,
                            const float* __restrict__ det_b,
                            float* __restrict__ out) {
    int b = blockIdx.x;
    int lane = threadIdx.x;
    __shared__ float pv[18];
    if (lane < 18) {
        float acc = det_b[lane];
        for (int c = 0; c < 128; c++)
            acc = fmaf(det_w[lane * 128 + c], g_mean[b * 128 + c] * (1.f / 16384.f), acc);
        pv[lane] = acc;
    }
    __syncthreads();
    if (lane != 0) return;

    for (int i = 0; i < 18; i++) out[b * 18 + i] = pv[i];

    float bx[3][4], sc[3], eff[3];
    bool conf[3];
    for (int a = 0; a < 3; a++) {
        for (int k = 0; k < 4; k++) bx[a][k] = pv[a * 6 + k];
        sc[a] = 1.f / (1.f + expf(-pv[a * 6 + 4]));
        conf[a] = sc[a] > 0.5f;
        eff[a] = conf[a] ? sc[a] : -INFINITY;
    }
    int order[3];
    bool used[3] = {false, false, false};
    for (int i = 0; i < 3; i++) {
        int best = -1;
        for (int a = 0; a < 3; a++)
            if (!used[a] && (best < 0 || eff[a] > eff[best])) best = a;
        order[i] = best;
        used[best] = true;
    }
    float ox1[3], oy1[3], ox2[3], oy2[3], area[3];
    for (int i = 0; i < 3; i++) {
        int a = order[i];
        ox1[i] = bx[a][0]; oy1[i] = bx[a][1]; ox2[i] = bx[a][2]; oy2[i] = bx[a][3];
        area[i] = (ox2[i] - ox1[i]) * (oy2[i] - oy1[i]);
    }
    bool keep_s[3];
    bool sup[3] = {false, false, false};
    for (int i = 0; i < 3; i++) {
        bool valid = !sup[i];
        keep_s[i] = valid;
        if (valid) {
            for (int j = i + 1; j < 3; j++) {
                float ix1 = fmaxf(ox1[i], ox1[j]);
                float iy1 = fmaxf(oy1[i], oy1[j]);
                float ix2 = fminf(ox2[i], ox2[j]);
                float iy2 = fminf(oy2[i], oy2[j]);
                float inter = fmaxf(ix2 - ix1, 0.f) * fmaxf(iy2 - iy1, 0.f);
                float iou = inter / (area[i] + area[j] - inter);
                if (iou > 0.5f) sup[j] = true;
            }
        }
    }
    bool kp[3];
    for (int i = 0; i < 3; i++) kp[order[i]] = keep_s[i];
    for (int a = 0; a < 3; a++) kp[a] = kp[a] && conf[a];

    for (int a = 0; a < 3; a++) {
        for (int k = 0; k < 4; k++) out[144 + b * 12 + a * 4 + k] = bx[a][k];
        out[240 + b * 3 + a] = sc[a];
        out[264 + b * 3 + a] = kp[a] ? 1.f : 0.f;
    }
}

// ===========================================================================
extern "C" void kernel_launch(void* const* d_in, const int* in_sizes, int n_in,
                              void* d_out, int out_size) {
    const float* x      = (const float*)d_in[0];
    const float* rgb_w1 = (const float*)d_in[1];
    const float* rgb_b1 = (const float*)d_in[2];
    const float* rgb_w2 = (const float*)d_in[3];
    const float* rgb_b2 = (const float*)d_in[4];
    const float* ir_w1  = (const float*)d_in[5];
    const float* ir_b1  = (const float*)d_in[6];
    const float* ir_w2  = (const float*)d_in[7];
    const float* ir_b2  = (const float*)d_in[8];
    const float* fuse_w = (const float*)d_in[9];
    const float* fuse_b = (const float*)d_in[10];
    const float* det_w  = (const float*)d_in[11];
    const float* det_b  = (const float*)d_in[12];
    float* out = (float*)d_out;

    prep_kernel<<<(N_PREP + 255) / 256, 256>>>();
    xform_kernel<<<(N_XF + 255) / 256, 256>>>(rgb_w1, ir_w1, rgb_w2, ir_w2, fuse_w);

    conv1_mma<<<8192, 256>>>(x, rgb_b1, ir_b1);
    conv2_mma<<<4096, 256>>>(rgb_b2, ir_b2);
    fuse_mma<<<1024, 256>>>(fuse_b);
    head_kernel<<<8, 32>>>(det_w, det_b, out);
}